// round 6
// baseline (speedup 1.0000x reference)
#include <cuda_runtime.h>
#include <cstdint>

#define DM 2048
static __device__ float g_q [128*2048];
static __device__ float g_kn[128*2048];
static __device__ float g_vn[128*2048];
static __device__ float g_ao[128*2048];

__device__ __forceinline__ uint32_t f2t(float x){
    uint32_t r; asm("cvt.rna.tf32.f32 %0,%1;":"=r"(r):"f"(x)); return r;
}
__device__ __forceinline__ void mma8(float* c,uint32_t a0,uint32_t a1,uint32_t a2,uint32_t a3,
                                     uint32_t b0,uint32_t b1){
    asm volatile("mma.sync.aligned.m16n8k8.row.col.f32.tf32.tf32.f32 "
        "{%0,%1,%2,%3},{%4,%5,%6,%7},{%8,%9},{%0,%1,%2,%3};"
        :"+f"(c[0]),"+f"(c[1]),"+f"(c[2]),"+f"(c[3])
        :"r"(a0),"r"(a1),"r"(a2),"r"(a3),"r"(b0),"r"(b1));
}

// C[128,2048] = A @ W + b, 3xTF32. MODE0: x -> q/k/v scatter. MODE1: g_ao -> out.
template<int MODE>
__global__ __launch_bounds__(256) void gemm_k(const float* __restrict__ A,
    const float* __restrict__ W0,const float* __restrict__ W1,const float* __restrict__ W2,
    const float* __restrict__ B0,const float* __restrict__ B1,const float* __restrict__ B2,
    float* __restrict__ O)
{
    __shared__ float Xs[128*36], Ws[32*68];
    int tid=threadIdx.x, lane=tid&31, warp=tid>>5, tg=lane&3, gid=lane>>2;
    int sel = MODE? 0 : blockIdx.y;
    const float* W  = sel==0?W0: sel==1?W1:W2;
    const float* Bi = sel==0?B0: sel==1?B1:B2;
    const float* Ap = MODE? g_ao : A;
    int n0 = blockIdx.x*64, m0 = warp*16;
    float acc[8][4];
    #pragma unroll
    for(int i=0;i<8;i++){acc[i][0]=acc[i][1]=acc[i][2]=acc[i][3]=0.f;}
    float4 xr[4], wr[2];
    #pragma unroll
    for(int j=0;j<4;j++){int id=tid+j*256; xr[j]=*(const float4*)&Ap[(id>>3)*DM+((id&7)<<2)];}
    #pragma unroll
    for(int j=0;j<2;j++){int id=tid+j*256; wr[j]=*(const float4*)&W[(id>>4)*DM+n0+((id&15)<<2)];}
    for(int kc=0;kc<64;kc++){
        #pragma unroll
        for(int j=0;j<4;j++){int id=tid+j*256; *(float4*)&Xs[(id>>3)*36+((id&7)<<2)]=xr[j];}
        #pragma unroll
        for(int j=0;j<2;j++){int id=tid+j*256; *(float4*)&Ws[(id>>4)*68+((id&15)<<2)]=wr[j];}
        __syncthreads();
        if(kc<63){
            int k1=(kc+1)*32;
            #pragma unroll
            for(int j=0;j<4;j++){int id=tid+j*256; xr[j]=*(const float4*)&Ap[(id>>3)*DM+k1+((id&7)<<2)];}
            #pragma unroll
            for(int j=0;j<2;j++){int id=tid+j*256; wr[j]=*(const float4*)&W[(k1+(id>>4))*DM+n0+((id&15)<<2)];}
        }
        #pragma unroll
        for(int kk=0;kk<32;kk+=8){
            float a0=Xs[(m0+gid)*36+kk+tg],   a1=Xs[(m0+gid+8)*36+kk+tg];
            float a2=Xs[(m0+gid)*36+kk+tg+4], a3=Xs[(m0+gid+8)*36+kk+tg+4];
            uint32_t h0=f2t(a0),h1=f2t(a1),h2=f2t(a2),h3=f2t(a3);
            uint32_t l0=f2t(a0-__uint_as_float(h0)),l1=f2t(a1-__uint_as_float(h1));
            uint32_t l2=f2t(a2-__uint_as_float(h2)),l3=f2t(a3-__uint_as_float(h3));
            #pragma unroll
            for(int nt=0;nt<8;nt++){
                float b0=Ws[(kk+tg)*68+nt*8+gid], b1=Ws[(kk+tg+4)*68+nt*8+gid];
                uint32_t bh0=f2t(b0), bh1=f2t(b1);
                uint32_t bl0=f2t(b0-__uint_as_float(bh0)), bl1=f2t(b1-__uint_as_float(bh1));
                mma8(acc[nt],h0,h1,h2,h3,bh0,bh1);
                mma8(acc[nt],l0,l1,l2,l3,bh0,bh1);
                mma8(acc[nt],h0,h1,h2,h3,bl0,bl1);
            }
        }
        __syncthreads();
    }
    #pragma unroll
    for(int nt=0;nt<8;nt++){
        #pragma unroll
        for(int c=0;c<4;c++){
            int row=m0+gid+((c>>1)<<3);
            int col=n0+nt*8+2*tg+(c&1);
            float v=acc[nt][c]+Bi[col];
            if(MODE){ O[row*DM+col]=v; }
            else{
                float* dst = sel==0?g_q: sel==1?g_kn:g_vn;
                dst[(((row>>4)<<4)|(col>>7))*2048 + (row&15)*128 + (col&127)] = v;
            }
        }
    }
}

// Flash attention: one CTA per (b,h). Each warp owns interleaved 16-key groups,
// private online softmax + 16x128 O accumulator, merged once at the end.
__global__ __launch_bounds__(256) void attn_k(const float* __restrict__ kc_,
                                              const float* __restrict__ vc_)
{
    __shared__ float qs[16*132];
    __shared__ float ps[8][16*20];
    __shared__ float Osum[16*132];
    __shared__ float Lsum[16];
    __shared__ float m8[8][16];
    int tid=threadIdx.x, lane=tid&31, warp=tid>>5, tg=lane&3, gid=lane>>2;
    int bh=blockIdx.x;
    const float cs = 0.08838834764831843f * 1.4426950408889634f; // hd^-0.5 * log2(e)
    for(int j=tid;j<512;j+=256){
        float4 v=*(const float4*)&g_q[bh*2048+j*4];
        int r=j>>5, c4=(j&31)<<2;
        qs[r*132+c4]=v.x*cs; qs[r*132+c4+1]=v.y*cs;
        qs[r*132+c4+2]=v.z*cs; qs[r*132+c4+3]=v.w*cs;
    }
    for(int j=tid;j<16*132;j+=256) Osum[j]=0.f;
    if(tid<16) Lsum[tid]=0.f;
    __syncthreads();
    const float* Kc = kc_ + (size_t)bh*4096*128;
    const float* Vc = vc_ + (size_t)bh*4096*128;
    float accO[16][4];
    #pragma unroll
    for(int i=0;i<16;i++){accO[i][0]=accO[i][1]=accO[i][2]=accO[i][3]=0.f;}
    float m0=-1e30f,m1=-1e30f,l0=0.f,l1=0.f;

    for(int g=warp; g<257; g+=8){
        const float* Kp = (g<256)? Kc+(size_t)g*2048 : g_kn+(size_t)bh*2048;
        const float* Vp = (g<256)? Vc+(size_t)g*2048 : g_vn+(size_t)bh*2048;
        float sA[2][4], sB[2][4];
        #pragma unroll
        for(int nt=0;nt<2;nt++){ for(int c=0;c<4;c++){sA[nt][c]=0.f;sB[nt][c]=0.f;} }
        #pragma unroll
        for(int kk=0;kk<128;kk+=8){
            uint32_t a0=f2t(qs[gid*132+kk+tg]),     a1=f2t(qs[(gid+8)*132+kk+tg]);
            uint32_t a2=f2t(qs[gid*132+kk+tg+4]),   a3=f2t(qs[(gid+8)*132+kk+tg+4]);
            #pragma unroll
            for(int nt=0;nt<2;nt++){
                float b0=Kp[(nt*8+gid)*128+kk+tg], b1=Kp[(nt*8+gid)*128+kk+tg+4];
                uint32_t bh0=f2t(b0),bh1=f2t(b1);
                uint32_t bl0=f2t(b0-__uint_as_float(bh0)),bl1=f2t(b1-__uint_as_float(bh1));
                mma8(sA[nt],a0,a1,a2,a3,bh0,bh1);
                mma8(sB[nt],a0,a1,a2,a3,bl0,bl1);
            }
        }
        float s[2][4];
        #pragma unroll
        for(int nt=0;nt<2;nt++){
            #pragma unroll
            for(int c=0;c<4;c++){
                float v=sA[nt][c]+sB[nt][c];
                if(g==256){
                    int col=nt*8+2*tg+(c&1), row=gid+((c>>1)<<3);
                    if(col>row) v=-1e30f;
                }
                s[nt][c]=v;
            }
        }
        float x0=fmaxf(fmaxf(s[0][0],s[0][1]),fmaxf(s[1][0],s[1][1]));
        float x1=fmaxf(fmaxf(s[0][2],s[0][3]),fmaxf(s[1][2],s[1][3]));
        x0=fmaxf(x0,__shfl_xor_sync(~0u,x0,1)); x0=fmaxf(x0,__shfl_xor_sync(~0u,x0,2));
        x1=fmaxf(x1,__shfl_xor_sync(~0u,x1,1)); x1=fmaxf(x1,__shfl_xor_sync(~0u,x1,2));
        float nm0=fmaxf(m0,x0), nm1=fmaxf(m1,x1);
        float f0=exp2f(m0-nm0), f1=exp2f(m1-nm1);
        m0=nm0; m1=nm1;
        float p[2][4], su0=0.f, su1=0.f;
        #pragma unroll
        for(int nt=0;nt<2;nt++){
            p[nt][0]=exp2f(s[nt][0]-nm0); p[nt][1]=exp2f(s[nt][1]-nm0);
            p[nt][2]=exp2f(s[nt][2]-nm1); p[nt][3]=exp2f(s[nt][3]-nm1);
            su0+=p[nt][0]+p[nt][1]; su1+=p[nt][2]+p[nt][3];
        }
        su0+=__shfl_xor_sync(~0u,su0,1); su0+=__shfl_xor_sync(~0u,su0,2);
        su1+=__shfl_xor_sync(~0u,su1,1); su1+=__shfl_xor_sync(~0u,su1,2);
        l0=l0*f0+su0; l1=l1*f1+su1;
        #pragma unroll
        for(int i=0;i<16;i++){accO[i][0]*=f0;accO[i][1]*=f0;accO[i][2]*=f1;accO[i][3]*=f1;}
        float* pw=ps[warp];
        #pragma unroll
        for(int nt=0;nt<2;nt++){
            pw[gid*20+nt*8+2*tg]=p[nt][0];     pw[gid*20+nt*8+2*tg+1]=p[nt][1];
            pw[(gid+8)*20+nt*8+2*tg]=p[nt][2]; pw[(gid+8)*20+nt*8+2*tg+1]=p[nt][3];
        }
        __syncwarp();
        #pragma unroll
        for(int ks=0;ks<2;ks++){
            float pa0=pw[gid*20+ks*8+tg],   pa1=pw[(gid+8)*20+ks*8+tg];
            float pa2=pw[gid*20+ks*8+tg+4], pa3=pw[(gid+8)*20+ks*8+tg+4];
            uint32_t h0=f2t(pa0),h1=f2t(pa1),h2=f2t(pa2),h3=f2t(pa3);
            uint32_t q0=f2t(pa0-__uint_as_float(h0)),q1=f2t(pa1-__uint_as_float(h1));
            uint32_t q2=f2t(pa2-__uint_as_float(h2)),q3=f2t(pa3-__uint_as_float(h3));
            #pragma unroll
            for(int nt=0;nt<16;nt++){
                uint32_t b0=f2t(Vp[(ks*8+tg)*128+nt*8+gid]);
                uint32_t b1=f2t(Vp[(ks*8+tg+4)*128+nt*8+gid]);
                mma8(accO[nt],h0,h1,h2,h3,b0,b1);
                mma8(accO[nt],q0,q1,q2,q3,b0,b1);
            }
        }
        __syncwarp();
    }
    if(tg==0){ m8[warp][gid]=m0; m8[warp][gid+8]=m1; }
    __syncthreads();
    float M0=-1e30f,M1=-1e30f;
    #pragma unroll
    for(int w=0;w<8;w++){ M0=fmaxf(M0,m8[w][gid]); M1=fmaxf(M1,m8[w][gid+8]); }
    float sc0=exp2f(m0-M0), sc1=exp2f(m1-M1);
    if(tg==0){ atomicAdd(&Lsum[gid],l0*sc0); atomicAdd(&Lsum[gid+8],l1*sc1); }
    #pragma unroll
    for(int nt=0;nt<16;nt++){
        atomicAdd(&Osum[gid*132+nt*8+2*tg],       accO[nt][0]*sc0);
        atomicAdd(&Osum[gid*132+nt*8+2*tg+1],     accO[nt][1]*sc0);
        atomicAdd(&Osum[(gid+8)*132+nt*8+2*tg],   accO[nt][2]*sc1);
        atomicAdd(&Osum[(gid+8)*132+nt*8+2*tg+1], accO[nt][3]*sc1);
    }
    __syncthreads();
    int b=bh>>4, h=bh&15;
    for(int j=tid;j<2048;j+=256){
        int s_=j>>7, d=j&127;
        g_ao[(b*16+s_)*2048 + h*128 + d] = Osum[s_*132+d]/Lsum[s_];
    }
}

extern "C" void kernel_launch(void* const* d_in, const int* in_sizes, int n_in,
                              void* d_out, int out_size)
{
    const float* x =(const float*)d_in[0];
    const float* kc=(const float*)d_in[1];
    const float* vc=(const float*)d_in[2];
    const float* Wq=(const float*)d_in[3]; const float* bq=(const float*)d_in[4];
    const float* Wk=(const float*)d_in[5]; const float* bk=(const float*)d_in[6];
    const float* Wv=(const float*)d_in[7]; const float* bv=(const float*)d_in[8];
    const float* Wo=(const float*)d_in[9]; const float* bo=(const float*)d_in[10];
    gemm_k<0><<<dim3(32,3),256>>>(x,Wq,Wk,Wv,bq,bk,bv,nullptr);
    attn_k<<<128,256>>>(kc,vc);
    gemm_k<1><<<dim3(32,1),256>>>(nullptr,Wo,Wo,Wo,bo,bo,bo,(float*)d_out);
}

// round 7
// speedup vs baseline: 1.4270x; 1.4270x over previous
#include <cuda_runtime.h>
#include <cstdint>

#define DM 2048
static __device__ float g_q [128*2048];
static __device__ float g_kn[128*2048];
static __device__ float g_vn[128*2048];
static __device__ float g_ao[128*2048];

__device__ __forceinline__ uint32_t f2t(float x){
    uint32_t r; asm("cvt.rna.tf32.f32 %0,%1;":"=r"(r):"f"(x)); return r;
}
__device__ __forceinline__ float tf(float x){ return __uint_as_float(f2t(x)); }
__device__ __forceinline__ float4 t4(float4 v){
    v.x=tf(v.x); v.y=tf(v.y); v.z=tf(v.z); v.w=tf(v.w); return v;
}
__device__ __forceinline__ float ex2(float x){
    float r; asm("ex2.approx.ftz.f32 %0,%1;":"=f"(r):"f"(x)); return r;
}
__device__ __forceinline__ void mma8(float* c,uint32_t a0,uint32_t a1,uint32_t a2,uint32_t a3,
                                     uint32_t b0,uint32_t b1){
    asm volatile("mma.sync.aligned.m16n8k8.row.col.f32.tf32.tf32.f32 "
        "{%0,%1,%2,%3},{%4,%5,%6,%7},{%8,%9},{%0,%1,%2,%3};"
        :"+f"(c[0]),"+f"(c[1]),"+f"(c[2]),"+f"(c[3])
        :"r"(a0),"r"(a1),"r"(a2),"r"(a3),"r"(b0),"r"(b1));
}

// C[128,2048] = A @ W + b, 1xTF32 (operands pre-rounded at staging).
// MODE0: x -> q/k/v scatter. MODE1: g_ao -> out.
template<int MODE>
__global__ __launch_bounds__(256) void gemm_k(const float* __restrict__ A,
    const float* __restrict__ W0,const float* __restrict__ W1,const float* __restrict__ W2,
    const float* __restrict__ B0,const float* __restrict__ B1,const float* __restrict__ B2,
    float* __restrict__ O)
{
    __shared__ float Xs[128*36], Ws[32*72];
    int tid=threadIdx.x, lane=tid&31, warp=tid>>5, tg=lane&3, gid=lane>>2;
    int sel = MODE? 0 : blockIdx.y;
    const float* W  = sel==0?W0: sel==1?W1:W2;
    const float* Bi = sel==0?B0: sel==1?B1:B2;
    const float* Ap = MODE? g_ao : A;
    int n0 = blockIdx.x*64, m0 = warp*16;
    float acc[8][4];
    #pragma unroll
    for(int i=0;i<8;i++){acc[i][0]=acc[i][1]=acc[i][2]=acc[i][3]=0.f;}
    float4 xr[4], wr[2];
    #pragma unroll
    for(int j=0;j<4;j++){int id=tid+j*256; xr[j]=*(const float4*)&Ap[(id>>3)*DM+((id&7)<<2)];}
    #pragma unroll
    for(int j=0;j<2;j++){int id=tid+j*256; wr[j]=*(const float4*)&W[(id>>4)*DM+n0+((id&15)<<2)];}
    for(int kc=0;kc<64;kc++){
        #pragma unroll
        for(int j=0;j<4;j++){int id=tid+j*256; *(float4*)&Xs[(id>>3)*36+((id&7)<<2)]=t4(xr[j]);}
        #pragma unroll
        for(int j=0;j<2;j++){int id=tid+j*256; *(float4*)&Ws[(id>>4)*72+((id&15)<<2)]=t4(wr[j]);}
        __syncthreads();
        if(kc<63){
            int k1=(kc+1)*32;
            #pragma unroll
            for(int j=0;j<4;j++){int id=tid+j*256; xr[j]=*(const float4*)&Ap[(id>>3)*DM+k1+((id&7)<<2)];}
            #pragma unroll
            for(int j=0;j<2;j++){int id=tid+j*256; wr[j]=*(const float4*)&W[(k1+(id>>4))*DM+n0+((id&15)<<2)];}
        }
        #pragma unroll
        for(int kk=0;kk<32;kk+=8){
            uint32_t a0=__float_as_uint(Xs[(m0+gid)*36+kk+tg]);
            uint32_t a1=__float_as_uint(Xs[(m0+gid+8)*36+kk+tg]);
            uint32_t a2=__float_as_uint(Xs[(m0+gid)*36+kk+tg+4]);
            uint32_t a3=__float_as_uint(Xs[(m0+gid+8)*36+kk+tg+4]);
            #pragma unroll
            for(int nt=0;nt<8;nt++){
                uint32_t b0=__float_as_uint(Ws[(kk+tg)*72+nt*8+gid]);
                uint32_t b1=__float_as_uint(Ws[(kk+tg+4)*72+nt*8+gid]);
                mma8(acc[nt],a0,a1,a2,a3,b0,b1);
            }
        }
        __syncthreads();
    }
    #pragma unroll
    for(int nt=0;nt<8;nt++){
        #pragma unroll
        for(int c=0;c<4;c++){
            int row=m0+gid+((c>>1)<<3);
            int col=n0+nt*8+2*tg+(c&1);
            float v=acc[nt][c]+Bi[col];
            if(MODE){ O[row*DM+col]=v; }
            else{
                float* dst = sel==0?g_q: sel==1?g_kn:g_vn;
                dst[(((row>>4)<<4)|(col>>7))*2048 + (row&15)*128 + (col&127)] = v;
            }
        }
    }
}

// Flash attention: one CTA per (b,h), 16 warps. Each warp owns interleaved
// 16-key groups with private online softmax + 16x128 O accumulator; merged
// once at the end through shared memory.
#define NW 16
__global__ __launch_bounds__(512) void attn_k(const float* __restrict__ kc_,
                                              const float* __restrict__ vc_)
{
    __shared__ float qs[16*132];      // tf32-rounded, prescaled
    __shared__ float ps[NW][16*20];
    __shared__ float Osum[16*132];
    __shared__ float Lsum[16];
    __shared__ float msh[NW][16];
    int tid=threadIdx.x, lane=tid&31, warp=tid>>5, tg=lane&3, gid=lane>>2;
    int bh=blockIdx.x;
    const float cs = 0.08838834764831843f * 1.4426950408889634f; // hd^-0.5 * log2(e)
    {
        int j=tid;  // 512 threads, 512 float4s
        float4 v=*(const float4*)&g_q[bh*2048+j*4];
        int r=j>>5, c4=(j&31)<<2;
        qs[r*132+c4+0]=tf(v.x*cs); qs[r*132+c4+1]=tf(v.y*cs);
        qs[r*132+c4+2]=tf(v.z*cs); qs[r*132+c4+3]=tf(v.w*cs);
    }
    for(int j=tid;j<16*132;j+=512) Osum[j]=0.f;
    if(tid<16) Lsum[tid]=0.f;
    __syncthreads();
    const float* Kc = kc_ + (size_t)bh*4096*128;
    const float* Vc = vc_ + (size_t)bh*4096*128;
    float accO[16][4];
    #pragma unroll
    for(int i=0;i<16;i++){accO[i][0]=accO[i][1]=accO[i][2]=accO[i][3]=0.f;}
    float m0=-1e30f,m1=-1e30f,l0=0.f,l1=0.f;

    for(int g=warp; g<257; g+=NW){
        const float* Kp = (g<256)? Kc+(size_t)g*2048 : g_kn+(size_t)bh*2048;
        const float* Vp = (g<256)? Vc+(size_t)g*2048 : g_vn+(size_t)bh*2048;
        float s[2][4];
        #pragma unroll
        for(int nt=0;nt<2;nt++){s[nt][0]=s[nt][1]=s[nt][2]=s[nt][3]=0.f;}
        #pragma unroll
        for(int kk=0;kk<128;kk+=8){
            uint32_t a0=__float_as_uint(qs[gid*132+kk+tg]);
            uint32_t a1=__float_as_uint(qs[(gid+8)*132+kk+tg]);
            uint32_t a2=__float_as_uint(qs[gid*132+kk+tg+4]);
            uint32_t a3=__float_as_uint(qs[(gid+8)*132+kk+tg+4]);
            #pragma unroll
            for(int nt=0;nt<2;nt++){
                uint32_t b0=f2t(Kp[(nt*8+gid)*128+kk+tg]);
                uint32_t b1=f2t(Kp[(nt*8+gid)*128+kk+tg+4]);
                mma8(s[nt],a0,a1,a2,a3,b0,b1);
            }
        }
        if(g==256){
            #pragma unroll
            for(int nt=0;nt<2;nt++){
                #pragma unroll
                for(int c=0;c<4;c++){
                    int col=nt*8+2*tg+(c&1), row=gid+((c>>1)<<3);
                    if(col>row) s[nt][c]=-1e30f;
                }
            }
        }
        float x0=fmaxf(fmaxf(s[0][0],s[0][1]),fmaxf(s[1][0],s[1][1]));
        float x1=fmaxf(fmaxf(s[0][2],s[0][3]),fmaxf(s[1][2],s[1][3]));
        x0=fmaxf(x0,__shfl_xor_sync(~0u,x0,1)); x0=fmaxf(x0,__shfl_xor_sync(~0u,x0,2));
        x1=fmaxf(x1,__shfl_xor_sync(~0u,x1,1)); x1=fmaxf(x1,__shfl_xor_sync(~0u,x1,2));
        float nm0=fmaxf(m0,x0), nm1=fmaxf(m1,x1);
        float f0=ex2(m0-nm0), f1=ex2(m1-nm1);
        m0=nm0; m1=nm1;
        float p[2][4], su0=0.f, su1=0.f;
        #pragma unroll
        for(int nt=0;nt<2;nt++){
            p[nt][0]=ex2(s[nt][0]-nm0); p[nt][1]=ex2(s[nt][1]-nm0);
            p[nt][2]=ex2(s[nt][2]-nm1); p[nt][3]=ex2(s[nt][3]-nm1);
            su0+=p[nt][0]+p[nt][1]; su1+=p[nt][2]+p[nt][3];
        }
        su0+=__shfl_xor_sync(~0u,su0,1); su0+=__shfl_xor_sync(~0u,su0,2);
        su1+=__shfl_xor_sync(~0u,su1,1); su1+=__shfl_xor_sync(~0u,su1,2);
        l0=l0*f0+su0; l1=l1*f1+su1;
        #pragma unroll
        for(int i=0;i<16;i++){accO[i][0]*=f0;accO[i][1]*=f0;accO[i][2]*=f1;accO[i][3]*=f1;}
        float* pw=ps[warp];
        #pragma unroll
        for(int nt=0;nt<2;nt++){
            pw[gid*20+nt*8+2*tg]=p[nt][0];     pw[gid*20+nt*8+2*tg+1]=p[nt][1];
            pw[(gid+8)*20+nt*8+2*tg]=p[nt][2]; pw[(gid+8)*20+nt*8+2*tg+1]=p[nt][3];
        }
        __syncwarp();
        #pragma unroll
        for(int ks=0;ks<2;ks++){
            uint32_t h0=f2t(pw[gid*20+ks*8+tg]);
            uint32_t h1=f2t(pw[(gid+8)*20+ks*8+tg]);
            uint32_t h2=f2t(pw[gid*20+ks*8+tg+4]);
            uint32_t h3=f2t(pw[(gid+8)*20+ks*8+tg+4]);
            #pragma unroll
            for(int nt=0;nt<16;nt++){
                uint32_t b0=f2t(Vp[(ks*8+tg)*128+nt*8+gid]);
                uint32_t b1=f2t(Vp[(ks*8+tg+4)*128+nt*8+gid]);
                mma8(accO[nt],h0,h1,h2,h3,b0,b1);
            }
        }
        __syncwarp();
    }
    if(tg==0){ msh[warp][gid]=m0; msh[warp][gid+8]=m1; }
    __syncthreads();
    float M0=-1e30f,M1=-1e30f;
    #pragma unroll
    for(int w=0;w<NW;w++){ M0=fmaxf(M0,msh[w][gid]); M1=fmaxf(M1,msh[w][gid+8]); }
    float sc0=ex2(m0-M0), sc1=ex2(m1-M1);
    if(tg==0){ atomicAdd(&Lsum[gid],l0*sc0); atomicAdd(&Lsum[gid+8],l1*sc1); }
    #pragma unroll
    for(int nt=0;nt<16;nt++){
        atomicAdd(&Osum[gid*132+nt*8+2*tg],       accO[nt][0]*sc0);
        atomicAdd(&Osum[gid*132+nt*8+2*tg+1],     accO[nt][1]*sc0);
        atomicAdd(&Osum[(gid+8)*132+nt*8+2*tg],   accO[nt][2]*sc1);
        atomicAdd(&Osum[(gid+8)*132+nt*8+2*tg+1], accO[nt][3]*sc1);
    }
    __syncthreads();
    int b=bh>>4, h=bh&15;
    for(int j=tid;j<2048;j+=512){
        int s_=j>>7, d=j&127;
        g_ao[(b*16+s_)*2048 + h*128 + d] = Osum[s_*132+d]/Lsum[s_];
    }
}

extern "C" void kernel_launch(void* const* d_in, const int* in_sizes, int n_in,
                              void* d_out, int out_size)
{
    const float* x =(const float*)d_in[0];
    const float* kc=(const float*)d_in[1];
    const float* vc=(const float*)d_in[2];
    const float* Wq=(const float*)d_in[3]; const float* bq=(const float*)d_in[4];
    const float* Wk=(const float*)d_in[5]; const float* bk=(const float*)d_in[6];
    const float* Wv=(const float*)d_in[7]; const float* bv=(const float*)d_in[8];
    const float* Wo=(const float*)d_in[9]; const float* bo=(const float*)d_in[10];
    gemm_k<0><<<dim3(32,3),256>>>(x,Wq,Wk,Wv,bq,bk,bv,nullptr);
    attn_k<<<128,512>>>(kc,vc);
    gemm_k<1><<<dim3(32,1),256>>>(nullptr,Wo,Wo,Wo,bo,bo,bo,(float*)d_out);
}

// round 8
// speedup vs baseline: 1.6235x; 1.1377x over previous
#include <cuda_runtime.h>
#include <cstdint>

#define DM 2048
static __device__ float g_q [128*2048];
static __device__ float g_kn[128*2048];
static __device__ float g_vn[128*2048];
static __device__ float g_ao[128*2048];

__device__ __forceinline__ uint32_t f2t(float x){
    uint32_t r; asm("cvt.rna.tf32.f32 %0,%1;":"=r"(r):"f"(x)); return r;
}
__device__ __forceinline__ float tf(float x){ return __uint_as_float(f2t(x)); }
__device__ __forceinline__ float ex2(float x){
    float r; asm("ex2.approx.ftz.f32 %0,%1;":"=f"(r):"f"(x)); return r;
}
__device__ __forceinline__ void mma8(float* c,uint32_t a0,uint32_t a1,uint32_t a2,uint32_t a3,
                                     uint32_t b0,uint32_t b1){
    asm volatile("mma.sync.aligned.m16n8k8.row.col.f32.tf32.tf32.f32 "
        "{%0,%1,%2,%3},{%4,%5,%6,%7},{%8,%9},{%0,%1,%2,%3};"
        :"+f"(c[0]),"+f"(c[1]),"+f"(c[2]),"+f"(c[3])
        :"r"(a0),"r"(a1),"r"(a2),"r"(a3),"r"(b0),"r"(b1));
}
__device__ __forceinline__ void cpa16(float* s, const float* g){
    uint32_t sa=(uint32_t)__cvta_generic_to_shared(s);
    asm volatile("cp.async.cg.shared.global [%0],[%1],16;" :: "r"(sa),"l"(g));
}
__device__ __forceinline__ void cpcommit(){ asm volatile("cp.async.commit_group;"); }
__device__ __forceinline__ void cpwait0(){ asm volatile("cp.async.wait_group 0;"); }
__device__ __forceinline__ void cpwait1(){ asm volatile("cp.async.wait_group 1;"); }

// ======================= GEMM: C[128,2048]=A@W+b ==========================
// 2-stage cp.async pipeline, 1xTF32 (cvt inline after LDS).
// MODE0: x -> q/k/v scatter.  MODE1: g_ao -> out.
#define GEMM_SMEM ((2*128*36 + 2*32*72)*4)

template<int MODE>
__global__ __launch_bounds__(256) void gemm_k(const float* __restrict__ A,
    const float* __restrict__ W0,const float* __restrict__ W1,const float* __restrict__ W2,
    const float* __restrict__ B0,const float* __restrict__ B1,const float* __restrict__ B2,
    float* __restrict__ O)
{
    extern __shared__ float sm[];
    float* Xs = sm;             // [2][128*36]
    float* Ws = sm + 2*4608;    // [2][32*72]
    int tid=threadIdx.x, lane=tid&31, warp=tid>>5, tg=lane&3, gid=lane>>2;
    int sel = MODE? 0 : blockIdx.y;
    const float* W  = sel==0?W0: sel==1?W1:W2;
    const float* Bi = sel==0?B0: sel==1?B1:B2;
    const float* Ap = MODE? g_ao : A;
    int n0 = blockIdx.x*64, m0 = warp*16;
    float acc[8][4];
    #pragma unroll
    for(int i=0;i<8;i++){acc[i][0]=acc[i][1]=acc[i][2]=acc[i][3]=0.f;}

    // stage issuer for chunk kc into buffer b
    auto issue=[&](int b,int kc){
        #pragma unroll
        for(int j=0;j<4;j++){ int id=tid+j*256; int r=id>>3, c4=(id&7)<<2;
            cpa16(&Xs[b*4608 + r*36 + c4], &Ap[r*DM + kc*32 + c4]); }
        #pragma unroll
        for(int j=0;j<2;j++){ int id=tid+j*256; int r=id>>4, c4=(id&15)<<2;
            cpa16(&Ws[b*2304 + r*72 + c4], &W[(kc*32+r)*DM + n0 + c4]); }
        cpcommit();
    };
    issue(0,0);
    for(int kc=0;kc<64;kc++){
        if(kc<63){ issue((kc+1)&1, kc+1); cpwait1(); } else cpwait0();
        __syncthreads();
        const float* xb = &Xs[(kc&1)*4608];
        const float* wb = &Ws[(kc&1)*2304];
        #pragma unroll
        for(int kk=0;kk<32;kk+=8){
            uint32_t a0=f2t(xb[(m0+gid)*36+kk+tg]);
            uint32_t a1=f2t(xb[(m0+gid+8)*36+kk+tg]);
            uint32_t a2=f2t(xb[(m0+gid)*36+kk+tg+4]);
            uint32_t a3=f2t(xb[(m0+gid+8)*36+kk+tg+4]);
            #pragma unroll
            for(int nt=0;nt<8;nt++){
                uint32_t b0=f2t(wb[(kk+tg)*72+nt*8+gid]);
                uint32_t b1=f2t(wb[(kk+tg+4)*72+nt*8+gid]);
                mma8(acc[nt],a0,a1,a2,a3,b0,b1);
            }
        }
        __syncthreads();
    }
    #pragma unroll
    for(int nt=0;nt<8;nt++){
        #pragma unroll
        for(int c=0;c<4;c++){
            int row=m0+gid+((c>>1)<<3);
            int col=n0+nt*8+2*tg+(c&1);
            float v=acc[nt][c]+Bi[col];
            if(MODE){ O[row*DM+col]=v; }
            else{
                float* dst = sel==0?g_q: sel==1?g_kn:g_vn;
                dst[(((row>>4)<<4)|(col>>7))*2048 + (row&15)*128 + (col&127)] = v;
            }
        }
    }
}

// ======================= Flash attention ==================================
// 1 CTA per (b,h), 8 warps. 64-key tiles staged via cp.async double buffer.
// Warp w owns keys [8w,8w+8) of each tile; private online softmax + 16x128
// accO; merged once at the end. Warps 0-1 handle the 16 new keys in a tail.
#define KS_STR 132
#define VS_STR 136
#define KBUF (64*KS_STR)
#define VBUF (64*VS_STR)
#define ATTN_SMEM ((2*KBUF + 2*VBUF + 16*132 + 8*192 + 16*132 + 16 + 8*16)*4)

__global__ __launch_bounds__(256) void attn_k(const float* __restrict__ kc_,
                                              const float* __restrict__ vc_)
{
    extern __shared__ float sm[];
    float* Ks   = sm;                       // [2][64*132]
    float* Vs   = sm + 2*KBUF;              // [2][64*136]
    float* qs   = Vs + 2*VBUF;              // [16*132]
    float* psm  = qs + 16*132;              // [8][16*12]
    float* Osum = psm + 8*192;              // [16*132]
    float* Lsum = Osum + 16*132;            // [16]
    float* msh  = Lsum + 16;                // [8][16]
    int tid=threadIdx.x, lane=tid&31, warp=tid>>5, tg=lane&3, gid=lane>>2;
    int bh=blockIdx.x;
    const float cs = 0.08838834764831843f * 1.4426950408889634f; // hd^-0.5*log2(e)
    #pragma unroll
    for(int j=tid;j<512;j+=256){
        float4 v=*(const float4*)&g_q[bh*2048+j*4];
        int r=j>>5, c4=(j&31)<<2;
        qs[r*132+c4+0]=tf(v.x*cs); qs[r*132+c4+1]=tf(v.y*cs);
        qs[r*132+c4+2]=tf(v.z*cs); qs[r*132+c4+3]=tf(v.w*cs);
    }
    for(int j=tid;j<16*132;j+=256) Osum[j]=0.f;
    if(tid<16) Lsum[tid]=0.f;
    const float* Kc = kc_ + (size_t)bh*4096*128;
    const float* Vc = vc_ + (size_t)bh*4096*128;

    auto issue=[&](int b,int t){
        #pragma unroll
        for(int j=0;j<8;j++){ int id=tid+j*256; int r=id>>5, c4=(id&31)<<2;
            cpa16(&Ks[b*KBUF + r*KS_STR + c4], &Kc[(size_t)(t*64+r)*128 + c4]); }
        #pragma unroll
        for(int j=0;j<8;j++){ int id=tid+j*256; int r=id>>5, c4=(id&31)<<2;
            cpa16(&Vs[b*VBUF + r*VS_STR + c4], &Vc[(size_t)(t*64+r)*128 + c4]); }
        cpcommit();
    };

    float accO[16][4];
    #pragma unroll
    for(int i=0;i<16;i++){accO[i][0]=accO[i][1]=accO[i][2]=accO[i][3]=0.f;}
    float m0=-1e30f,m1=-1e30f,l0=0.f,l1=0.f;
    float* pw = psm + warp*192;

    issue(0,0);
    for(int t=0;t<64;t++){
        if(t<63){ issue((t+1)&1, t+1); cpwait1(); } else cpwait0();
        __syncthreads();
        const float* Kb=&Ks[(t&1)*KBUF];
        const float* Vb=&Vs[(t&1)*VBUF];
        float s[4]={0.f,0.f,0.f,0.f};
        #pragma unroll
        for(int kk=0;kk<128;kk+=8){
            uint32_t a0=__float_as_uint(qs[gid*132+kk+tg]);
            uint32_t a1=__float_as_uint(qs[(gid+8)*132+kk+tg]);
            uint32_t a2=__float_as_uint(qs[gid*132+kk+tg+4]);
            uint32_t a3=__float_as_uint(qs[(gid+8)*132+kk+tg+4]);
            uint32_t b0=f2t(Kb[(warp*8+gid)*KS_STR+kk+tg]);
            uint32_t b1=f2t(Kb[(warp*8+gid)*KS_STR+kk+tg+4]);
            mma8(s,a0,a1,a2,a3,b0,b1);
        }
        float x0=fmaxf(s[0],s[1]), x1=fmaxf(s[2],s[3]);
        x0=fmaxf(x0,__shfl_xor_sync(~0u,x0,1)); x0=fmaxf(x0,__shfl_xor_sync(~0u,x0,2));
        x1=fmaxf(x1,__shfl_xor_sync(~0u,x1,1)); x1=fmaxf(x1,__shfl_xor_sync(~0u,x1,2));
        float nm0=fmaxf(m0,x0), nm1=fmaxf(m1,x1);
        float f0=ex2(m0-nm0), f1=ex2(m1-nm1);
        m0=nm0; m1=nm1;
        float p0=ex2(s[0]-nm0), p1=ex2(s[1]-nm0);
        float p2=ex2(s[2]-nm1), p3=ex2(s[3]-nm1);
        float su0=p0+p1, su1=p2+p3;
        su0+=__shfl_xor_sync(~0u,su0,1); su0+=__shfl_xor_sync(~0u,su0,2);
        su1+=__shfl_xor_sync(~0u,su1,1); su1+=__shfl_xor_sync(~0u,su1,2);
        l0=l0*f0+su0; l1=l1*f1+su1;
        #pragma unroll
        for(int i=0;i<16;i++){accO[i][0]*=f0;accO[i][1]*=f0;accO[i][2]*=f1;accO[i][3]*=f1;}
        pw[gid*12+2*tg]=p0;     pw[gid*12+2*tg+1]=p1;
        pw[(gid+8)*12+2*tg]=p2; pw[(gid+8)*12+2*tg+1]=p3;
        __syncwarp();
        uint32_t h0=f2t(pw[gid*12+tg]);
        uint32_t h1=f2t(pw[(gid+8)*12+tg]);
        uint32_t h2=f2t(pw[gid*12+tg+4]);
        uint32_t h3=f2t(pw[(gid+8)*12+tg+4]);
        #pragma unroll
        for(int nt=0;nt<16;nt++){
            uint32_t b0=f2t(Vb[(warp*8+tg)*VS_STR+nt*8+gid]);
            uint32_t b1=f2t(Vb[(warp*8+tg+4)*VS_STR+nt*8+gid]);
            mma8(accO[nt],h0,h1,h2,h3,b0,b1);
        }
        __syncthreads();
    }

    // tail: 16 new keys (warps 0-1, 8 keys each) with causal mask
    if(warp<2){
        const float* Kp = g_kn + bh*2048 + warp*8*128;
        const float* Vp = g_vn + bh*2048 + warp*8*128;
        float s[4]={0.f,0.f,0.f,0.f};
        #pragma unroll
        for(int kk=0;kk<128;kk+=8){
            uint32_t a0=__float_as_uint(qs[gid*132+kk+tg]);
            uint32_t a1=__float_as_uint(qs[(gid+8)*132+kk+tg]);
            uint32_t a2=__float_as_uint(qs[gid*132+kk+tg+4]);
            uint32_t a3=__float_as_uint(qs[(gid+8)*132+kk+tg+4]);
            uint32_t b0=f2t(Kp[gid*128+kk+tg]);
            uint32_t b1=f2t(Kp[gid*128+kk+tg+4]);
            mma8(s,a0,a1,a2,a3,b0,b1);
        }
        #pragma unroll
        for(int c=0;c<4;c++){
            int col16=warp*8+2*tg+(c&1), row=gid+((c>>1)<<3);
            if(col16>row) s[c]=-1e30f;
        }
        float x0=fmaxf(s[0],s[1]), x1=fmaxf(s[2],s[3]);
        x0=fmaxf(x0,__shfl_xor_sync(~0u,x0,1)); x0=fmaxf(x0,__shfl_xor_sync(~0u,x0,2));
        x1=fmaxf(x1,__shfl_xor_sync(~0u,x1,1)); x1=fmaxf(x1,__shfl_xor_sync(~0u,x1,2));
        float nm0=fmaxf(m0,x0), nm1=fmaxf(m1,x1);
        float f0=ex2(m0-nm0), f1=ex2(m1-nm1);
        m0=nm0; m1=nm1;
        float p0=ex2(s[0]-nm0), p1=ex2(s[1]-nm0);
        float p2=ex2(s[2]-nm1), p3=ex2(s[3]-nm1);
        float su0=p0+p1, su1=p2+p3;
        su0+=__shfl_xor_sync(~0u,su0,1); su0+=__shfl_xor_sync(~0u,su0,2);
        su1+=__shfl_xor_sync(~0u,su1,1); su1+=__shfl_xor_sync(~0u,su1,2);
        l0=l0*f0+su0; l1=l1*f1+su1;
        #pragma unroll
        for(int i=0;i<16;i++){accO[i][0]*=f0;accO[i][1]*=f0;accO[i][2]*=f1;accO[i][3]*=f1;}
        pw[gid*12+2*tg]=p0;     pw[gid*12+2*tg+1]=p1;
        pw[(gid+8)*12+2*tg]=p2; pw[(gid+8)*12+2*tg+1]=p3;
        __syncwarp();
        uint32_t h0=f2t(pw[gid*12+tg]);
        uint32_t h1=f2t(pw[(gid+8)*12+tg]);
        uint32_t h2=f2t(pw[gid*12+tg+4]);
        uint32_t h3=f2t(pw[(gid+8)*12+tg+4]);
        #pragma unroll
        for(int nt=0;nt<16;nt++){
            uint32_t b0=f2t(Vp[tg*128+nt*8+gid]);
            uint32_t b1=f2t(Vp[(tg+4)*128+nt*8+gid]);
            mma8(accO[nt],h0,h1,h2,h3,b0,b1);
        }
    }

    // merge across 8 warps
    if(tg==0){ msh[warp*16+gid]=m0; msh[warp*16+gid+8]=m1; }
    __syncthreads();
    float M0=-1e30f,M1=-1e30f;
    #pragma unroll
    for(int w=0;w<8;w++){ M0=fmaxf(M0,msh[w*16+gid]); M1=fmaxf(M1,msh[w*16+gid+8]); }
    float sc0=ex2(m0-M0), sc1=ex2(m1-M1);
    if(tg==0){ atomicAdd(&Lsum[gid],l0*sc0); atomicAdd(&Lsum[gid+8],l1*sc1); }
    #pragma unroll
    for(int nt=0;nt<16;nt++){
        atomicAdd(&Osum[gid*132+nt*8+2*tg],       accO[nt][0]*sc0);
        atomicAdd(&Osum[gid*132+nt*8+2*tg+1],     accO[nt][1]*sc0);
        atomicAdd(&Osum[(gid+8)*132+nt*8+2*tg],   accO[nt][2]*sc1);
        atomicAdd(&Osum[(gid+8)*132+nt*8+2*tg+1], accO[nt][3]*sc1);
    }
    __syncthreads();
    int b=bh>>4, h=bh&15;
    for(int j=tid;j<2048;j+=256){
        int s_=j>>7, d=j&127;
        g_ao[(b*16+s_)*2048 + h*128 + d] = Osum[s_*132+d]/Lsum[s_];
    }
}

extern "C" void kernel_launch(void* const* d_in, const int* in_sizes, int n_in,
                              void* d_out, int out_size)
{
    const float* x =(const float*)d_in[0];
    const float* kc=(const float*)d_in[1];
    const float* vc=(const float*)d_in[2];
    const float* Wq=(const float*)d_in[3]; const float* bq=(const float*)d_in[4];
    const float* Wk=(const float*)d_in[5]; const float* bk=(const float*)d_in[6];
    const float* Wv=(const float*)d_in[7]; const float* bv=(const float*)d_in[8];
    const float* Wo=(const float*)d_in[9]; const float* bo=(const float*)d_in[10];
    cudaFuncSetAttribute(gemm_k<0>, cudaFuncAttributeMaxDynamicSharedMemorySize, GEMM_SMEM);
    cudaFuncSetAttribute(gemm_k<1>, cudaFuncAttributeMaxDynamicSharedMemorySize, GEMM_SMEM);
    cudaFuncSetAttribute(attn_k,    cudaFuncAttributeMaxDynamicSharedMemorySize, ATTN_SMEM);
    gemm_k<0><<<dim3(32,3),256,GEMM_SMEM>>>(x,Wq,Wk,Wv,bq,bk,bv,nullptr);
    attn_k<<<128,256,ATTN_SMEM>>>(kc,vc);
    gemm_k<1><<<dim3(32,1),256,GEMM_SMEM>>>(nullptr,Wo,Wo,Wo,bo,bo,bo,(float*)d_out);
}

// round 9
// speedup vs baseline: 2.3836x; 1.4682x over previous
#include <cuda_runtime.h>
#include <cstdint>

#define DM 2048
static __device__ float g_q [128*2048];
static __device__ float g_kn[128*2048];
static __device__ float g_vn[128*2048];
static __device__ float g_ao[128*2048];
static __device__ float g_part[4*128*2048];   // split-K partials for out-proj

__device__ __forceinline__ uint32_t f2t(float x){
    uint32_t r; asm("cvt.rna.tf32.f32 %0,%1;":"=r"(r):"f"(x)); return r;
}
__device__ __forceinline__ float tf(float x){ return __uint_as_float(f2t(x)); }
__device__ __forceinline__ float ex2(float x){
    float r; asm("ex2.approx.ftz.f32 %0,%1;":"=f"(r):"f"(x)); return r;
}
__device__ __forceinline__ void mma8(float* c,uint32_t a0,uint32_t a1,uint32_t a2,uint32_t a3,
                                     uint32_t b0,uint32_t b1){
    asm volatile("mma.sync.aligned.m16n8k8.row.col.f32.tf32.tf32.f32 "
        "{%0,%1,%2,%3},{%4,%5,%6,%7},{%8,%9},{%0,%1,%2,%3};"
        :"+f"(c[0]),"+f"(c[1]),"+f"(c[2]),"+f"(c[3])
        :"r"(a0),"r"(a1),"r"(a2),"r"(a3),"r"(b0),"r"(b1));
}
__device__ __forceinline__ void cpa16(float* s, const float* g){
    uint32_t sa=(uint32_t)__cvta_generic_to_shared(s);
    asm volatile("cp.async.cg.shared.global [%0],[%1],16;" :: "r"(sa),"l"(g));
}
__device__ __forceinline__ void cpcommit(){ asm volatile("cp.async.commit_group;"); }
__device__ __forceinline__ void cpwait0(){ asm volatile("cp.async.wait_group 0;"); }
__device__ __forceinline__ void cpwait1(){ asm volatile("cp.async.wait_group 1;"); }

// ======================= GEMM =============================================
// 512 threads, 16 warps (8M x 2N), warp tile 16x32, 2-stage cp.async.
// MODE0: x @ {Wq,Wk,Wv} + b -> scatter to g_q/g_kn/g_vn (sel = blockIdx.y).
// MODE1: g_ao @ Wo, K-slice blockIdx.y (512 wide) -> g_part (no bias).
#define GEMM_SMEM ((2*128*36 + 2*32*72)*4)

template<int MODE>
__global__ __launch_bounds__(512) void gemm_k(const float* __restrict__ A,
    const float* __restrict__ W0,const float* __restrict__ W1,const float* __restrict__ W2,
    const float* __restrict__ B0,const float* __restrict__ B1,const float* __restrict__ B2)
{
    extern __shared__ float sm[];
    float* Xs = sm;             // [2][128*36]
    float* Ws = sm + 2*4608;    // [2][32*72]
    int tid=threadIdx.x, lane=tid&31, warp=tid>>5, tg=lane&3, gid=lane>>2;
    int sel = MODE? 0 : blockIdx.y;
    const float* W  = sel==0?W0: sel==1?W1:W2;
    const float* Bi = sel==0?B0: sel==1?B1:B2;
    const float* Ap = MODE? g_ao : A;
    int n0 = blockIdx.x*64;
    int kcb = MODE? blockIdx.y*16 : 0;
    int kcn = MODE? 16 : 64;
    int m0 = (warp&7)*16, nb = (warp>>3)*32;
    float acc[4][4];
    #pragma unroll
    for(int i=0;i<4;i++){acc[i][0]=acc[i][1]=acc[i][2]=acc[i][3]=0.f;}

    auto issue=[&](int b,int kc){
        #pragma unroll
        for(int j=0;j<2;j++){ int id=tid+j*512; int r=id>>3, c4=(id&7)<<2;
            cpa16(&Xs[b*4608 + r*36 + c4], &Ap[r*DM + kc*32 + c4]); }
        { int r=tid>>4, c4=(tid&15)<<2;
            cpa16(&Ws[b*2304 + r*72 + c4], &W[(kc*32+r)*DM + n0 + c4]); }
        cpcommit();
    };
    issue(0,kcb);
    for(int i=0;i<kcn;i++){
        if(i<kcn-1){ issue((i+1)&1, kcb+i+1); cpwait1(); } else cpwait0();
        __syncthreads();
        const float* xb = &Xs[(i&1)*4608];
        const float* wb = &Ws[(i&1)*2304];
        #pragma unroll
        for(int kk=0;kk<32;kk+=8){
            uint32_t a0=f2t(xb[(m0+gid)*36+kk+tg]);
            uint32_t a1=f2t(xb[(m0+gid+8)*36+kk+tg]);
            uint32_t a2=f2t(xb[(m0+gid)*36+kk+tg+4]);
            uint32_t a3=f2t(xb[(m0+gid+8)*36+kk+tg+4]);
            #pragma unroll
            for(int nt=0;nt<4;nt++){
                uint32_t b0=f2t(wb[(kk+tg)*72+nb+nt*8+gid]);
                uint32_t b1=f2t(wb[(kk+tg+4)*72+nb+nt*8+gid]);
                mma8(acc[nt],a0,a1,a2,a3,b0,b1);
            }
        }
        __syncthreads();
    }
    #pragma unroll
    for(int nt=0;nt<4;nt++){
        #pragma unroll
        for(int c=0;c<4;c++){
            int row=m0+gid+((c>>1)<<3);
            int col=n0+nb+nt*8+2*tg+(c&1);
            if(MODE){
                g_part[blockIdx.y*262144 + row*DM + col] = acc[nt][c];
            }else{
                float v=acc[nt][c]+Bi[col];
                float* dst = sel==0?g_q: sel==1?g_kn:g_vn;
                dst[(((row>>4)<<4)|(col>>7))*2048 + (row&15)*128 + (col&127)] = v;
            }
        }
    }
}

// reduce split-K partials + bias -> d_out
__global__ __launch_bounds__(512) void reduce_k(const float* __restrict__ Bo,
                                                float* __restrict__ O)
{
    int idx = blockIdx.x*512 + threadIdx.x;   // one float4 each; 65536 total
    int base = idx*4, col = base & 2047;
    float4 p0=*(const float4*)&g_part[base];
    float4 p1=*(const float4*)&g_part[262144+base];
    float4 p2=*(const float4*)&g_part[524288+base];
    float4 p3=*(const float4*)&g_part[786432+base];
    float4 b=*(const float4*)&Bo[col];
    float4 o;
    o.x=p0.x+p1.x+p2.x+p3.x+b.x; o.y=p0.y+p1.y+p2.y+p3.y+b.y;
    o.z=p0.z+p1.z+p2.z+p3.z+b.z; o.w=p0.w+p1.w+p2.w+p3.w+b.w;
    *(float4*)&O[base]=o;
}

// ======================= Flash attention ==================================
#define KS_STR 132
#define VS_STR 136
#define KBUF (64*KS_STR)
#define VBUF (64*VS_STR)
#define ATTN_SMEM ((2*KBUF + 2*VBUF + 16*132 + 8*192 + 16*132 + 16 + 8*16)*4)

__global__ __launch_bounds__(256) void attn_k(const float* __restrict__ kc_,
                                              const float* __restrict__ vc_)
{
    extern __shared__ float sm[];
    float* Ks   = sm;
    float* Vs   = sm + 2*KBUF;
    float* qs   = Vs + 2*VBUF;
    float* psm  = qs + 16*132;
    float* Osum = psm + 8*192;
    float* Lsum = Osum + 16*132;
    float* msh  = Lsum + 16;
    int tid=threadIdx.x, lane=tid&31, warp=tid>>5, tg=lane&3, gid=lane>>2;
    int bh=blockIdx.x;
    const float cs = 0.08838834764831843f * 1.4426950408889634f;
    #pragma unroll
    for(int j=tid;j<512;j+=256){
        float4 v=*(const float4*)&g_q[bh*2048+j*4];
        int r=j>>5, c4=(j&31)<<2;
        qs[r*132+c4+0]=tf(v.x*cs); qs[r*132+c4+1]=tf(v.y*cs);
        qs[r*132+c4+2]=tf(v.z*cs); qs[r*132+c4+3]=tf(v.w*cs);
    }
    for(int j=tid;j<16*132;j+=256) Osum[j]=0.f;
    if(tid<16) Lsum[tid]=0.f;
    const float* Kc = kc_ + (size_t)bh*4096*128;
    const float* Vc = vc_ + (size_t)bh*4096*128;

    auto issue=[&](int b,int t){
        #pragma unroll
        for(int j=0;j<8;j++){ int id=tid+j*256; int r=id>>5, c4=(id&31)<<2;
            cpa16(&Ks[b*KBUF + r*KS_STR + c4], &Kc[(size_t)(t*64+r)*128 + c4]); }
        #pragma unroll
        for(int j=0;j<8;j++){ int id=tid+j*256; int r=id>>5, c4=(id&31)<<2;
            cpa16(&Vs[b*VBUF + r*VS_STR + c4], &Vc[(size_t)(t*64+r)*128 + c4]); }
        cpcommit();
    };
    issue(0,0);
    __syncthreads();   // qs ready (also before first tile compute)

    // hoist Q fragments to registers (rounded+scaled already)
    uint32_t aq0[16],aq1[16],aq2[16],aq3[16];
    #pragma unroll
    for(int k8=0;k8<16;k8++){
        aq0[k8]=__float_as_uint(qs[gid*132+k8*8+tg]);
        aq1[k8]=__float_as_uint(qs[(gid+8)*132+k8*8+tg]);
        aq2[k8]=__float_as_uint(qs[gid*132+k8*8+tg+4]);
        aq3[k8]=__float_as_uint(qs[(gid+8)*132+k8*8+tg+4]);
    }

    float accO[16][4];
    #pragma unroll
    for(int i=0;i<16;i++){accO[i][0]=accO[i][1]=accO[i][2]=accO[i][3]=0.f;}
    float m0=-1e30f,m1=-1e30f,l0=0.f,l1=0.f;
    float* pw = psm + warp*192;

    for(int t=0;t<64;t++){
        if(t<63){ issue((t+1)&1, t+1); cpwait1(); } else cpwait0();
        __syncthreads();
        const float* Kb=&Ks[(t&1)*KBUF];
        const float* Vb=&Vs[(t&1)*VBUF];
        float s[4]={0.f,0.f,0.f,0.f};
        #pragma unroll
        for(int k8=0;k8<16;k8++){
            uint32_t b0=f2t(Kb[(warp*8+gid)*KS_STR+k8*8+tg]);
            uint32_t b1=f2t(Kb[(warp*8+gid)*KS_STR+k8*8+tg+4]);
            mma8(s,aq0[k8],aq1[k8],aq2[k8],aq3[k8],b0,b1);
        }
        float x0=fmaxf(s[0],s[1]), x1=fmaxf(s[2],s[3]);
        x0=fmaxf(x0,__shfl_xor_sync(~0u,x0,1)); x0=fmaxf(x0,__shfl_xor_sync(~0u,x0,2));
        x1=fmaxf(x1,__shfl_xor_sync(~0u,x1,1)); x1=fmaxf(x1,__shfl_xor_sync(~0u,x1,2));
        bool upd = __any_sync(~0u,(x0>m0)||(x1>m1));
        float nm0=fmaxf(m0,x0), nm1=fmaxf(m1,x1);
        float f0=1.f,f1=1.f;
        if(upd){
            f0=ex2(m0-nm0); f1=ex2(m1-nm1);
            m0=nm0; m1=nm1;
            #pragma unroll
            for(int i=0;i<16;i++){accO[i][0]*=f0;accO[i][1]*=f0;accO[i][2]*=f1;accO[i][3]*=f1;}
        }
        float p0=ex2(s[0]-nm0), p1=ex2(s[1]-nm0);
        float p2=ex2(s[2]-nm1), p3=ex2(s[3]-nm1);
        float su0=p0+p1, su1=p2+p3;
        su0+=__shfl_xor_sync(~0u,su0,1); su0+=__shfl_xor_sync(~0u,su0,2);
        su1+=__shfl_xor_sync(~0u,su1,1); su1+=__shfl_xor_sync(~0u,su1,2);
        l0=l0*f0+su0; l1=l1*f1+su1;
        pw[gid*12+2*tg]=p0;     pw[gid*12+2*tg+1]=p1;
        pw[(gid+8)*12+2*tg]=p2; pw[(gid+8)*12+2*tg+1]=p3;
        __syncwarp();
        uint32_t h0=f2t(pw[gid*12+tg]);
        uint32_t h1=f2t(pw[(gid+8)*12+tg]);
        uint32_t h2=f2t(pw[gid*12+tg+4]);
        uint32_t h3=f2t(pw[(gid+8)*12+tg+4]);
        #pragma unroll
        for(int nt=0;nt<16;nt++){
            uint32_t b0=f2t(Vb[(warp*8+tg)*VS_STR+nt*8+gid]);
            uint32_t b1=f2t(Vb[(warp*8+tg+4)*VS_STR+nt*8+gid]);
            mma8(accO[nt],h0,h1,h2,h3,b0,b1);
        }
        __syncthreads();
    }

    // tail: 16 new keys (warps 0-1), causal mask
    if(warp<2){
        const float* Kp = g_kn + bh*2048 + warp*8*128;
        const float* Vp = g_vn + bh*2048 + warp*8*128;
        float s[4]={0.f,0.f,0.f,0.f};
        #pragma unroll
        for(int k8=0;k8<16;k8++){
            uint32_t b0=f2t(Kp[gid*128+k8*8+tg]);
            uint32_t b1=f2t(Kp[gid*128+k8*8+tg+4]);
            mma8(s,aq0[k8],aq1[k8],aq2[k8],aq3[k8],b0,b1);
        }
        #pragma unroll
        for(int c=0;c<4;c++){
            int col16=warp*8+2*tg+(c&1), row=gid+((c>>1)<<3);
            if(col16>row) s[c]=-1e30f;
        }
        float x0=fmaxf(s[0],s[1]), x1=fmaxf(s[2],s[3]);
        x0=fmaxf(x0,__shfl_xor_sync(~0u,x0,1)); x0=fmaxf(x0,__shfl_xor_sync(~0u,x0,2));
        x1=fmaxf(x1,__shfl_xor_sync(~0u,x1,1)); x1=fmaxf(x1,__shfl_xor_sync(~0u,x1,2));
        float nm0=fmaxf(m0,x0), nm1=fmaxf(m1,x1);
        float f0=ex2(m0-nm0), f1=ex2(m1-nm1);
        m0=nm0; m1=nm1;
        float p0=ex2(s[0]-nm0), p1=ex2(s[1]-nm0);
        float p2=ex2(s[2]-nm1), p3=ex2(s[3]-nm1);
        float su0=p0+p1, su1=p2+p3;
        su0+=__shfl_xor_sync(~0u,su0,1); su0+=__shfl_xor_sync(~0u,su0,2);
        su1+=__shfl_xor_sync(~0u,su1,1); su1+=__shfl_xor_sync(~0u,su1,2);
        l0=l0*f0+su0; l1=l1*f1+su1;
        #pragma unroll
        for(int i=0;i<16;i++){accO[i][0]*=f0;accO[i][1]*=f0;accO[i][2]*=f1;accO[i][3]*=f1;}
        pw[gid*12+2*tg]=p0;     pw[gid*12+2*tg+1]=p1;
        pw[(gid+8)*12+2*tg]=p2; pw[(gid+8)*12+2*tg+1]=p3;
        __syncwarp();
        uint32_t h0=f2t(pw[gid*12+tg]);
        uint32_t h1=f2t(pw[(gid+8)*12+tg]);
        uint32_t h2=f2t(pw[gid*12+tg+4]);
        uint32_t h3=f2t(pw[(gid+8)*12+tg+4]);
        #pragma unroll
        for(int nt=0;nt<16;nt++){
            uint32_t b0=f2t(Vp[tg*128+nt*8+gid]);
            uint32_t b1=f2t(Vp[(tg+4)*128+nt*8+gid]);
            mma8(accO[nt],h0,h1,h2,h3,b0,b1);
        }
    }

    // merge across 8 warps
    if(tg==0){ msh[warp*16+gid]=m0; msh[warp*16+gid+8]=m1; }
    __syncthreads();
    float M0=-1e30f,M1=-1e30f;
    #pragma unroll
    for(int w=0;w<8;w++){ M0=fmaxf(M0,msh[w*16+gid]); M1=fmaxf(M1,msh[w*16+gid+8]); }
    float sc0=ex2(m0-M0), sc1=ex2(m1-M1);
    if(tg==0){ atomicAdd(&Lsum[gid],l0*sc0); atomicAdd(&Lsum[gid+8],l1*sc1); }
    #pragma unroll
    for(int nt=0;nt<16;nt++){
        atomicAdd(&Osum[gid*132+nt*8+2*tg],       accO[nt][0]*sc0);
        atomicAdd(&Osum[gid*132+nt*8+2*tg+1],     accO[nt][1]*sc0);
        atomicAdd(&Osum[(gid+8)*132+nt*8+2*tg],   accO[nt][2]*sc1);
        atomicAdd(&Osum[(gid+8)*132+nt*8+2*tg+1], accO[nt][3]*sc1);
    }
    __syncthreads();
    int b=bh>>4, h=bh&15;
    for(int j=tid;j<2048;j+=256){
        int s_=j>>7, d=j&127;
        g_ao[(b*16+s_)*2048 + h*128 + d] = Osum[s_*132+d]/Lsum[s_];
    }
}

extern "C" void kernel_launch(void* const* d_in, const int* in_sizes, int n_in,
                              void* d_out, int out_size)
{
    const float* x =(const float*)d_in[0];
    const float* kc=(const float*)d_in[1];
    const float* vc=(const float*)d_in[2];
    const float* Wq=(const float*)d_in[3]; const float* bq=(const float*)d_in[4];
    const float* Wk=(const float*)d_in[5]; const float* bk=(const float*)d_in[6];
    const float* Wv=(const float*)d_in[7]; const float* bv=(const float*)d_in[8];
    const float* Wo=(const float*)d_in[9]; const float* bo=(const float*)d_in[10];
    cudaFuncSetAttribute(gemm_k<0>, cudaFuncAttributeMaxDynamicSharedMemorySize, GEMM_SMEM);
    cudaFuncSetAttribute(gemm_k<1>, cudaFuncAttributeMaxDynamicSharedMemorySize, GEMM_SMEM);
    cudaFuncSetAttribute(attn_k,    cudaFuncAttributeMaxDynamicSharedMemorySize, ATTN_SMEM);
    gemm_k<0><<<dim3(32,3),512,GEMM_SMEM>>>(x,Wq,Wk,Wv,bq,bk,bv);
    attn_k<<<128,256,ATTN_SMEM>>>(kc,vc);
    gemm_k<1><<<dim3(32,4),512,GEMM_SMEM>>>(nullptr,Wo,Wo,Wo,bo,bo,bo);
    reduce_k<<<128,512>>>(bo,(float*)d_out);
}